// round 1
// baseline (speedup 1.0000x reference)
#include <cuda_runtime.h>
#include <cuda_bf16.h>

// Grouped GEMM, fp32 baseline.
// Groups: (1024,1536,2048,2048,2560,2048,3072,2048), HIDDEN=2048, FFN=8192.
// All group offsets are multiples of 512, so a 128-row M-tile never crosses
// a group boundary -> plain GEMM with a per-tile weight-base lookup.

#define BM 128
#define BN 128
#define BK 16
#define TM 8
#define TN 8
#define NTHREADS 256

static constexpr int HIDDEN = 2048;
static constexpr int FFN    = 8192;
static constexpr int MTOTAL = 16384;

__device__ __constant__ int kGroupOff[9] = {
    0, 1024, 2560, 4608, 6656, 9216, 11264, 14336, 16384
};

__global__ __launch_bounds__(NTHREADS, 2)
void grouped_gemm_f32_kernel(const float* __restrict__ A,
                             const float* __restrict__ W,
                             float* __restrict__ C) {
    const int tid = threadIdx.x;
    const int tx  = tid & 15;   // N direction, 0..15
    const int ty  = tid >> 4;   // M direction, 0..15

    const int rowBase = blockIdx.y * BM;
    const int colBase = blockIdx.x * BN;

    // group lookup (8 compares, once per CTA)
    int g = 0;
#pragma unroll
    for (int i = 1; i < 8; ++i) {
        if (rowBase >= kGroupOff[i]) g = i;
    }
    const float* __restrict__ B = W + (size_t)g * HIDDEN * FFN;

    __shared__ float As[2][BK][BM];   // A stored transposed: As[k][m]
    __shared__ float Bs[2][BK][BN];   // Bs[k][n]

    // ---- global load mapping (float4 granularity) ----
    // A tile: 128 rows x 16 cols = 512 float4; 2 per thread.
    const int aRow0 = tid >> 2;             // 0..63
    const int aRow1 = aRow0 + 64;           // 64..127
    const int aCol  = (tid & 3) * 4;        // 0,4,8,12
    // B tile: 16 rows x 128 cols = 512 float4; 2 per thread.
    const int bRow0 = tid >> 5;             // 0..7
    const int bRow1 = bRow0 + 8;            // 8..15
    const int bCol  = (tid & 31) * 4;       // 0..124

    const float* aPtr0 = A + (size_t)(rowBase + aRow0) * HIDDEN + aCol;
    const float* aPtr1 = A + (size_t)(rowBase + aRow1) * HIDDEN + aCol;
    const float* bPtr0 = B + (size_t)bRow0 * FFN + colBase + bCol;
    const float* bPtr1 = B + (size_t)bRow1 * FFN + colBase + bCol;

    float acc[TM][TN];
#pragma unroll
    for (int i = 0; i < TM; ++i)
#pragma unroll
        for (int j = 0; j < TN; ++j) acc[i][j] = 0.0f;

    float4 ra0, ra1, rb0, rb1;

    // prologue: load tile 0
    ra0 = *(const float4*)(aPtr0);
    ra1 = *(const float4*)(aPtr1);
    rb0 = *(const float4*)(bPtr0);
    rb1 = *(const float4*)(bPtr1);
    {
        // store tile 0 into buffer 0
        As[0][aCol + 0][aRow0] = ra0.x;
        As[0][aCol + 1][aRow0] = ra0.y;
        As[0][aCol + 2][aRow0] = ra0.z;
        As[0][aCol + 3][aRow0] = ra0.w;
        As[0][aCol + 0][aRow1] = ra1.x;
        As[0][aCol + 1][aRow1] = ra1.y;
        As[0][aCol + 2][aRow1] = ra1.z;
        As[0][aCol + 3][aRow1] = ra1.w;
        *(float4*)&Bs[0][bRow0][bCol] = rb0;
        *(float4*)&Bs[0][bRow1][bCol] = rb1;
    }
    __syncthreads();

    const int nTiles = HIDDEN / BK;   // 128

    for (int kt = 0; kt < nTiles; ++kt) {
        const int buf = kt & 1;

        // stage next tile's global loads into registers (overlap with compute)
        if (kt + 1 < nTiles) {
            const int k0 = (kt + 1) * BK;
            ra0 = *(const float4*)(aPtr0 + k0);
            ra1 = *(const float4*)(aPtr1 + k0);
            rb0 = *(const float4*)(bPtr0 + (size_t)k0 * FFN);
            rb1 = *(const float4*)(bPtr1 + (size_t)k0 * FFN);
        }

        // compute on current buffer
#pragma unroll
        for (int kk = 0; kk < BK; ++kk) {
            float fa[TM], fb[TN];
            float4 t;
            t = *(const float4*)&As[buf][kk][ty * TM];
            fa[0] = t.x; fa[1] = t.y; fa[2] = t.z; fa[3] = t.w;
            t = *(const float4*)&As[buf][kk][ty * TM + 4];
            fa[4] = t.x; fa[5] = t.y; fa[6] = t.z; fa[7] = t.w;
            t = *(const float4*)&Bs[buf][kk][tx * TN];
            fb[0] = t.x; fb[1] = t.y; fb[2] = t.z; fb[3] = t.w;
            t = *(const float4*)&Bs[buf][kk][tx * TN + 4];
            fb[4] = t.x; fb[5] = t.y; fb[6] = t.z; fb[7] = t.w;
#pragma unroll
            for (int i = 0; i < TM; ++i)
#pragma unroll
                for (int j = 0; j < TN; ++j)
                    acc[i][j] = fmaf(fa[i], fb[j], acc[i][j]);
        }

        // commit staged tile into the other buffer
        if (kt + 1 < nTiles) {
            const int nb = buf ^ 1;
            As[nb][aCol + 0][aRow0] = ra0.x;
            As[nb][aCol + 1][aRow0] = ra0.y;
            As[nb][aCol + 2][aRow0] = ra0.z;
            As[nb][aCol + 3][aRow0] = ra0.w;
            As[nb][aCol + 0][aRow1] = ra1.x;
            As[nb][aCol + 1][aRow1] = ra1.y;
            As[nb][aCol + 2][aRow1] = ra1.z;
            As[nb][aCol + 3][aRow1] = ra1.w;
            *(float4*)&Bs[nb][bRow0][bCol] = rb0;
            *(float4*)&Bs[nb][bRow1][bCol] = rb1;
        }
        __syncthreads();
    }

    // epilogue: write 8x8 per thread as 2 float4 per row
    const int outRow = rowBase + ty * TM;
    const int outCol = colBase + tx * TN;
#pragma unroll
    for (int i = 0; i < TM; ++i) {
        float* cRow = C + (size_t)(outRow + i) * FFN + outCol;
        float4 v0 = make_float4(acc[i][0], acc[i][1], acc[i][2], acc[i][3]);
        float4 v1 = make_float4(acc[i][4], acc[i][5], acc[i][6], acc[i][7]);
        *(float4*)(cRow)     = v0;
        *(float4*)(cRow + 4) = v1;
    }
}

extern "C" void kernel_launch(void* const* d_in, const int* in_sizes, int n_in,
                              void* d_out, int out_size) {
    const float* A = (const float*)d_in[0];   // [16384, 2048]
    const float* W = (const float*)d_in[1];   // [8, 2048, 8192]
    float* C = (float*)d_out;                 // [16384, 8192]

    dim3 grid(FFN / BN, MTOTAL / BM);         // (64, 128)
    dim3 block(NTHREADS);
    grouped_gemm_f32_kernel<<<grid, block>>>(A, W, C);
}

// round 3
// speedup vs baseline: 3.3019x; 3.3019x over previous
#include <cuda_runtime.h>
#include <cuda_bf16.h>
#include <cstdint>

// Grouped GEMM via bf16-split HMMA (mma.sync): C = Ah*Bh + Al*Bh + Ah*Bl, fp32 accum.
// Groups: (1024,1536,2048,2048,2560,2048,3072,2048); HIDDEN=2048, FFN=8192.

static constexpr int HIDDEN = 2048;
static constexpr int FFN    = 8192;
static constexpr int MTOTAL = 16384;
static constexpr int NGROUPS = 8;

#define BM 128
#define BN 128
#define BK 32
static constexpr int NCHUNK = HIDDEN / BK;   // 64

// SMEM padded row: 32 bf16 + 8 pad = 40 elems = 80 bytes (keeps 16B alignment,
// 20-bank stride -> conflict-free ldmatrix over 8-row groups)
#define ROWB 80
#define OFF_AH 0
#define OFF_AL (BM * ROWB)            // 10240
#define OFF_BH (2 * BM * ROWB)        // 20480
#define OFF_BL (3 * BM * ROWB)        // 30720
#define STAGE  (4 * BM * ROWB)        // 40960
#define NSTAGE 3
#define SMEM_DYN (NSTAGE * STAGE)     // 122880

// ---- scratch (module-load allocated) ----
__device__ __nv_bfloat16 g_Ah[(size_t)MTOTAL * HIDDEN];
__device__ __nv_bfloat16 g_Al[(size_t)MTOTAL * HIDDEN];
__device__ __nv_bfloat16 g_Bh[(size_t)NGROUPS * FFN * HIDDEN];   // [g][n][k] K-major
__device__ __nv_bfloat16 g_Bl[(size_t)NGROUPS * FFN * HIDDEN];

__constant__ int kGroupOff[9] = {0, 1024, 2560, 4608, 6656, 9216, 11264, 14336, 16384};

// ================= conversion kernels =================

__global__ void convA_kernel(const float* __restrict__ A,
                             __nv_bfloat16* __restrict__ Ah,
                             __nv_bfloat16* __restrict__ Al) {
    size_t i = ((size_t)blockIdx.x * blockDim.x + threadIdx.x) * 4;
    float4 v = *(const float4*)(A + i);
    float f[4] = {v.x, v.y, v.z, v.w};
    __nv_bfloat16 h[4], l[4];
#pragma unroll
    for (int k = 0; k < 4; ++k) {
        h[k] = __float2bfloat16(f[k]);
        l[k] = __float2bfloat16(f[k] - __bfloat162float(h[k]));
    }
    ((__nv_bfloat162*)(Ah + i))[0] = __halves2bfloat162(h[0], h[1]);
    ((__nv_bfloat162*)(Ah + i))[1] = __halves2bfloat162(h[2], h[3]);
    ((__nv_bfloat162*)(Al + i))[0] = __halves2bfloat162(l[0], l[1]);
    ((__nv_bfloat162*)(Al + i))[1] = __halves2bfloat162(l[2], l[3]);
}

// Transpose W[g][k][n] -> Bh/Bl[g][n][k] (K contiguous), hi/lo split.
__global__ void convW_kernel(const float* __restrict__ W,
                             __nv_bfloat16* __restrict__ Bh,
                             __nv_bfloat16* __restrict__ Bl) {
    __shared__ float tile[32][33];
    const int g = blockIdx.z;
    const int nBase = blockIdx.x * 32;
    const int kBase = blockIdx.y * 32;
    const int tx = threadIdx.x;
    const int ty = threadIdx.y;
    const float* Wg = W + (size_t)g * HIDDEN * FFN;
#pragma unroll
    for (int i = 0; i < 4; ++i)
        tile[ty + 8 * i][tx] = Wg[(size_t)(kBase + ty + 8 * i) * FFN + nBase + tx];
    __syncthreads();
#pragma unroll
    for (int i = 0; i < 4; ++i) {
        float v = tile[tx][ty + 8 * i];
        __nv_bfloat16 h = __float2bfloat16(v);
        __nv_bfloat16 l = __float2bfloat16(v - __bfloat162float(h));
        size_t o = (size_t)g * FFN * HIDDEN + (size_t)(nBase + ty + 8 * i) * HIDDEN + kBase + tx;
        Bh[o] = h;
        Bl[o] = l;
    }
}

// ================= HMMA GEMM =================

__device__ __forceinline__ uint32_t smem_u32(const void* p) {
    uint32_t a;
    asm("{ .reg .u64 t; cvta.to.shared.u64 t, %1; cvt.u32.u64 %0, t; }" : "=r"(a) : "l"(p));
    return a;
}

__device__ __forceinline__ void cp16(uint32_t dst, const void* src) {
    asm volatile("cp.async.cg.shared.global [%0], [%1], 16;\n"
                 :: "r"(dst), "l"(__cvta_generic_to_global(src)));
}

__device__ __forceinline__ void ldmx4(uint32_t* r, uint32_t addr) {
    asm volatile("ldmatrix.sync.aligned.m8n8.x4.shared.b16 {%0,%1,%2,%3}, [%4];"
                 : "=r"(r[0]), "=r"(r[1]), "=r"(r[2]), "=r"(r[3]) : "r"(addr));
}

__device__ __forceinline__ void mma16816(float* c, const uint32_t* a, const uint32_t* b) {
    asm volatile(
        "mma.sync.aligned.m16n8k16.row.col.f32.bf16.bf16.f32 "
        "{%0,%1,%2,%3}, {%4,%5,%6,%7}, {%8,%9}, {%0,%1,%2,%3};"
        : "+f"(c[0]), "+f"(c[1]), "+f"(c[2]), "+f"(c[3])
        : "r"(a[0]), "r"(a[1]), "r"(a[2]), "r"(a[3]), "r"(b[0]), "r"(b[1]));
}

__global__ __launch_bounds__(256, 1)
void gemm_hmma_kernel(float* __restrict__ C) {
    extern __shared__ char smem[];
    const uint32_t sb = smem_u32(smem);

    const int tid  = threadIdx.x;
    const int warp = tid >> 5;
    const int lane = tid & 31;
    const int warpM = warp & 3;      // 0..3  -> M offset warpM*32
    const int warpN = warp >> 2;     // 0..1  -> N offset warpN*64

    const int rowBase = blockIdx.y * BM;
    const int colBase = blockIdx.x * BN;

    int g = 0;
#pragma unroll
    for (int i = 1; i < 8; ++i)
        if (rowBase >= kGroupOff[i]) g = i;

    const __nv_bfloat16* pAh = g_Ah + (size_t)rowBase * HIDDEN;
    const __nv_bfloat16* pAl = g_Al + (size_t)rowBase * HIDDEN;
    const __nv_bfloat16* pBh = g_Bh + (size_t)g * FFN * HIDDEN + (size_t)colBase * HIDDEN;
    const __nv_bfloat16* pBl = g_Bl + (size_t)g * FFN * HIDDEN + (size_t)colBase * HIDDEN;

    // ---- per-thread load slots: rows tid>>2 and +64, 16B chunk tid&3 ----
    const int lrow = tid >> 2;
    const int lkc  = tid & 3;
    const uint32_t so0 = (uint32_t)(lrow * ROWB + lkc * 16);
    const uint32_t so1 = so0 + 64 * ROWB;
    const size_t   go0 = (size_t)lrow * HIDDEN + lkc * 8;
    const size_t   go1 = go0 + (size_t)64 * HIDDEN;

    // ---- ldmatrix per-lane smem offsets ----
    // A (x4 covers m16 x k16): rows lanes mapping (t&15), k-half (t>>4)
    const uint32_t aOff = (uint32_t)((warpM * 32 + (lane & 15)) * ROWB + (lane >> 4) * 16);
    // B (x4 covers n16 x k16): n row (t&7)+8*(t>>4), k-half (t>>3)&1
    uint32_t bOff[4];
#pragma unroll
    for (int i = 0; i < 4; ++i)
        bOff[i] = (uint32_t)((warpN * 64 + i * 16 + (lane & 7) + 8 * (lane >> 4)) * ROWB
                             + ((lane >> 3) & 1) * 16);

    float acc[2][8][4];
#pragma unroll
    for (int i = 0; i < 2; ++i)
#pragma unroll
        for (int j = 0; j < 8; ++j)
#pragma unroll
            for (int q = 0; q < 4; ++q) acc[i][j][q] = 0.0f;

    // ---- prologue: stages 0,1 ----
#pragma unroll
    for (int j = 0; j < 2; ++j) {
        const uint32_t st = sb + j * STAGE;
        const size_t ko = (size_t)j * BK;
        cp16(st + OFF_AH + so0, pAh + go0 + ko);
        cp16(st + OFF_AH + so1, pAh + go1 + ko);
        cp16(st + OFF_AL + so0, pAl + go0 + ko);
        cp16(st + OFF_AL + so1, pAl + go1 + ko);
        cp16(st + OFF_BH + so0, pBh + go0 + ko);
        cp16(st + OFF_BH + so1, pBh + go1 + ko);
        cp16(st + OFF_BL + so0, pBl + go0 + ko);
        cp16(st + OFF_BL + so1, pBl + go1 + ko);
        asm volatile("cp.async.commit_group;" ::: "memory");
    }

    for (int j = 0; j < NCHUNK; ++j) {
        // issue loads for j+2
        if (j + 2 < NCHUNK) {
            const int jn = j + 2;
            const uint32_t st = sb + (jn % NSTAGE) * STAGE;
            const size_t ko = (size_t)jn * BK;
            cp16(st + OFF_AH + so0, pAh + go0 + ko);
            cp16(st + OFF_AH + so1, pAh + go1 + ko);
            cp16(st + OFF_AL + so0, pAl + go0 + ko);
            cp16(st + OFF_AL + so1, pAl + go1 + ko);
            cp16(st + OFF_BH + so0, pBh + go0 + ko);
            cp16(st + OFF_BH + so1, pBh + go1 + ko);
            cp16(st + OFF_BL + so0, pBl + go0 + ko);
            cp16(st + OFF_BL + so1, pBl + go1 + ko);
        }
        asm volatile("cp.async.commit_group;" ::: "memory");
        asm volatile("cp.async.wait_group %0;" :: "n"(2) : "memory");
        __syncthreads();

        const uint32_t st = sb + (j % NSTAGE) * STAGE;
#pragma unroll
        for (int s = 0; s < 2; ++s) {
            const uint32_t kb = s * 32;  // 16 bf16 = 32 bytes
            uint32_t ah[2][4], al[2][4], bh[4][4], bl[4][4];
            ldmx4(ah[0], st + OFF_AH + aOff + kb);
            ldmx4(ah[1], st + OFF_AH + aOff + 16 * ROWB + kb);
            ldmx4(al[0], st + OFF_AL + aOff + kb);
            ldmx4(al[1], st + OFF_AL + aOff + 16 * ROWB + kb);
#pragma unroll
            for (int i = 0; i < 4; ++i) {
                ldmx4(bh[i], st + OFF_BH + bOff[i] + kb);
                ldmx4(bl[i], st + OFF_BL + bOff[i] + kb);
            }
#pragma unroll
            for (int i = 0; i < 2; ++i) {
#pragma unroll
                for (int n = 0; n < 8; ++n) {
                    const uint32_t* bhf = &bh[n >> 1][(n & 1) * 2];
                    const uint32_t* blf = &bl[n >> 1][(n & 1) * 2];
                    mma16816(acc[i][n], ah[i], bhf);
                    mma16816(acc[i][n], al[i], bhf);
                    mma16816(acc[i][n], ah[i], blf);
                }
            }
        }
        __syncthreads();
    }

    // ---- epilogue ----
    const int mBase = rowBase + warpM * 32;
    const int nBase = colBase + warpN * 64;
#pragma unroll
    for (int i = 0; i < 2; ++i) {
#pragma unroll
        for (int n = 0; n < 8; ++n) {
            const int row0 = mBase + i * 16 + (lane >> 2);
            const int col  = nBase + n * 8 + (lane & 3) * 2;
            float2* d0 = (float2*)(C + (size_t)row0 * FFN + col);
            float2* d1 = (float2*)(C + (size_t)(row0 + 8) * FFN + col);
            *d0 = make_float2(acc[i][n][0], acc[i][n][1]);
            *d1 = make_float2(acc[i][n][2], acc[i][n][3]);
        }
    }
}

// ================= launch =================

extern "C" void kernel_launch(void* const* d_in, const int* in_sizes, int n_in,
                              void* d_out, int out_size) {
    const float* A = (const float*)d_in[0];   // [16384, 2048]
    const float* W = (const float*)d_in[1];   // [8, 2048, 8192]
    float* C = (float*)d_out;                 // [16384, 8192]

    __nv_bfloat16 *Ah, *Al, *Bh, *Bl;
    cudaGetSymbolAddress((void**)&Ah, g_Ah);
    cudaGetSymbolAddress((void**)&Al, g_Al);
    cudaGetSymbolAddress((void**)&Bh, g_Bh);
    cudaGetSymbolAddress((void**)&Bl, g_Bl);

    convA_kernel<<<(MTOTAL * HIDDEN) / (256 * 4), 256>>>(A, Ah, Al);
    convW_kernel<<<dim3(FFN / 32, HIDDEN / 32, NGROUPS), dim3(32, 8)>>>(W, Bh, Bl);

    cudaFuncSetAttribute(gemm_hmma_kernel,
                         cudaFuncAttributeMaxDynamicSharedMemorySize, SMEM_DYN);
    gemm_hmma_kernel<<<dim3(FFN / BN, MTOTAL / BM), 256, SMEM_DYN>>>(C);
}

// round 5
// speedup vs baseline: 3.8766x; 1.1741x over previous
#include <cuda_runtime.h>
#include <cuda_bf16.h>
#include <cstdint>

// Grouped GEMM via bf16-split HMMA: C = Ah*Bh + Al*Bh + Ah*Bl, fp32 accum.
// Tile 128x256, warp tile 64x64, 3-stage cp.async, panel-swizzled CTA order.

static constexpr int HIDDEN = 2048;
static constexpr int FFN    = 8192;
static constexpr int MTOTAL = 16384;
static constexpr int NGROUPS = 8;

#define BM 128
#define BN 256
#define BK 32
static constexpr int NCHUNK = HIDDEN / BK;   // 64

// padded SMEM row: 32 bf16 (64B) + 16B pad = 80B
#define ROWB 80
#define OFF_AH 0
#define OFF_AL (BM * ROWB)                  // 10240
#define OFF_BH (2 * BM * ROWB)              // 20480
#define OFF_BL (OFF_BH + BN * ROWB)         // 40960
#define STAGE  (OFF_BL + BN * ROWB)         // 61440
#define NSTAGE 3
#define SMEM_DYN (NSTAGE * STAGE)           // 184320

// ---- scratch ----
__device__ __nv_bfloat16 g_Ah[(size_t)MTOTAL * HIDDEN];
__device__ __nv_bfloat16 g_Al[(size_t)MTOTAL * HIDDEN];
__device__ __nv_bfloat16 g_Bh[(size_t)NGROUPS * FFN * HIDDEN];   // [g][n][k]
__device__ __nv_bfloat16 g_Bl[(size_t)NGROUPS * FFN * HIDDEN];

__constant__ int kGroupOff[9] = {0, 1024, 2560, 4608, 6656, 9216, 11264, 14336, 16384};

__device__ __forceinline__ uint32_t pack_bf2(__nv_bfloat16 lo, __nv_bfloat16 hi) {
    return (uint32_t)__bfloat16_as_ushort(lo) | ((uint32_t)__bfloat16_as_ushort(hi) << 16);
}

// ================= conversions =================

__global__ void convA_kernel(const float* __restrict__ A,
                             __nv_bfloat16* __restrict__ Ah,
                             __nv_bfloat16* __restrict__ Al) {
    size_t i = ((size_t)blockIdx.x * blockDim.x + threadIdx.x) * 4;
    float4 v = *(const float4*)(A + i);
    float f[4] = {v.x, v.y, v.z, v.w};
    __nv_bfloat16 h[4], l[4];
#pragma unroll
    for (int k = 0; k < 4; ++k) {
        h[k] = __float2bfloat16(f[k]);
        l[k] = __float2bfloat16(f[k] - __bfloat162float(h[k]));
    }
    ((uint32_t*)(Ah + i))[0] = pack_bf2(h[0], h[1]);
    ((uint32_t*)(Ah + i))[1] = pack_bf2(h[2], h[3]);
    ((uint32_t*)(Al + i))[0] = pack_bf2(l[0], l[1]);
    ((uint32_t*)(Al + i))[1] = pack_bf2(l[2], l[3]);
}

// W[g][k][n] -> Bh/Bl[g][n][k], 128k x 32n tiles, vectorized 32B stores.
__global__ __launch_bounds__(256)
void convW_kernel(const float* __restrict__ W,
                  __nv_bfloat16* __restrict__ Bh,
                  __nv_bfloat16* __restrict__ Bl) {
    __shared__ float tile[128][33];
    const int g = blockIdx.z;
    const int nBase = blockIdx.x * 32;
    const int kBase = blockIdx.y * 128;
    const int t = threadIdx.x;
    const float* Wg = W + (size_t)g * HIDDEN * FFN;

#pragma unroll
    for (int i = 0; i < 16; ++i) {
        int row = (t >> 5) + 8 * i;
        tile[row][t & 31] = Wg[(size_t)(kBase + row) * FFN + nBase + (t & 31)];
    }
    __syncthreads();

    const int n  = t & 31;
    const int k0 = (t >> 5) * 16;
    uint32_t hp[8], lp[8];
#pragma unroll
    for (int m = 0; m < 8; ++m) {
        float v0 = tile[k0 + 2 * m][n];
        float v1 = tile[k0 + 2 * m + 1][n];
        __nv_bfloat16 h0 = __float2bfloat16(v0);
        __nv_bfloat16 h1 = __float2bfloat16(v1);
        __nv_bfloat16 l0 = __float2bfloat16(v0 - __bfloat162float(h0));
        __nv_bfloat16 l1 = __float2bfloat16(v1 - __bfloat162float(h1));
        hp[m] = pack_bf2(h0, h1);
        lp[m] = pack_bf2(l0, l1);
    }
    size_t o = (size_t)g * FFN * HIDDEN + (size_t)(nBase + n) * HIDDEN + kBase + k0;
    uint4* dh = (uint4*)(Bh + o);
    uint4* dl = (uint4*)(Bl + o);
    dh[0] = make_uint4(hp[0], hp[1], hp[2], hp[3]);
    dh[1] = make_uint4(hp[4], hp[5], hp[6], hp[7]);
    dl[0] = make_uint4(lp[0], lp[1], lp[2], lp[3]);
    dl[1] = make_uint4(lp[4], lp[5], lp[6], lp[7]);
}

// ================= GEMM =================

__device__ __forceinline__ uint32_t smem_u32(const void* p) {
    uint32_t a;
    asm("{ .reg .u64 t; cvta.to.shared.u64 t, %1; cvt.u32.u64 %0, t; }" : "=r"(a) : "l"(p));
    return a;
}
__device__ __forceinline__ void cp16(uint32_t dst, const void* src) {
    asm volatile("cp.async.cg.shared.global [%0], [%1], 16;\n"
                 :: "r"(dst), "l"(__cvta_generic_to_global(src)));
}
__device__ __forceinline__ void ldmx4(uint32_t* r, uint32_t addr) {
    asm volatile("ldmatrix.sync.aligned.m8n8.x4.shared.b16 {%0,%1,%2,%3}, [%4];"
                 : "=r"(r[0]), "=r"(r[1]), "=r"(r[2]), "=r"(r[3]) : "r"(addr));
}
__device__ __forceinline__ void mma16816(float* c, const uint32_t* a, const uint32_t* b) {
    asm volatile(
        "mma.sync.aligned.m16n8k16.row.col.f32.bf16.bf16.f32 "
        "{%0,%1,%2,%3}, {%4,%5,%6,%7}, {%8,%9}, {%0,%1,%2,%3};"
        : "+f"(c[0]), "+f"(c[1]), "+f"(c[2]), "+f"(c[3])
        : "r"(a[0]), "r"(a[1]), "r"(a[2]), "r"(a[3]), "r"(b[0]), "r"(b[1]));
}

__global__ __launch_bounds__(256, 1)
void gemm_hmma_kernel(float* __restrict__ C) {
    extern __shared__ char smem[];
    const uint32_t sb = smem_u32(smem);

    const int tid  = threadIdx.x;
    const int warp = tid >> 5;
    const int lane = tid & 31;
    const int warpM = warp & 1;      // 0..1 -> M offset *64
    const int warpN = warp >> 1;     // 0..3 -> N offset *64

    // panel swizzle: 16 m-tiles per panel, column sweep within panel
    const int bid   = blockIdx.x;                 // 0..4095
    const int panel = bid >> 9;                   // /(16*32)
    const int idx   = bid & 511;
    const int rowBase = (panel * 16 + (idx & 15)) * BM;
    const int colBase = (idx >> 4) * BN;

    int g = 0;
#pragma unroll
    for (int i = 1; i < 8; ++i)
        if (rowBase >= kGroupOff[i]) g = i;

    const __nv_bfloat16* pAh = g_Ah + (size_t)rowBase * HIDDEN;
    const __nv_bfloat16* pAl = g_Al + (size_t)rowBase * HIDDEN;
    const __nv_bfloat16* pBh = g_Bh + (size_t)g * FFN * HIDDEN + (size_t)colBase * HIDDEN;
    const __nv_bfloat16* pBl = g_Bl + (size_t)g * FFN * HIDDEN + (size_t)colBase * HIDDEN;

    // copy slots: row = tid>>2 (+64i), 16B chunk = tid&3
    const int lrow = tid >> 2;
    const int lkc  = tid & 3;
    const uint32_t soA = (uint32_t)(lrow * ROWB + lkc * 16);
    const size_t   goA = (size_t)lrow * HIDDEN + lkc * 8;

    // ldmatrix offsets
    const uint32_t aOff = (uint32_t)((warpM * 64 + (lane & 15)) * ROWB + (lane >> 4) * 16);
    uint32_t bOff[4];
#pragma unroll
    for (int i = 0; i < 4; ++i)
        bOff[i] = (uint32_t)((warpN * 64 + i * 16 + (lane & 7) + 8 * ((lane >> 4) & 1)) * ROWB
                             + ((lane >> 3) & 1) * 16);

    float acc[4][8][4];
#pragma unroll
    for (int i = 0; i < 4; ++i)
#pragma unroll
        for (int n = 0; n < 8; ++n)
#pragma unroll
            for (int q = 0; q < 4; ++q) acc[i][n][q] = 0.0f;

#define ISSUE_LOADS(stagep, koff)                                            \
    do {                                                                     \
        const uint32_t st_ = (stagep);                                       \
        const size_t ko_ = (koff);                                           \
        cp16(st_ + OFF_AH + soA, pAh + goA + ko_);                           \
        cp16(st_ + OFF_AH + soA + 64 * ROWB, pAh + goA + 64 * HIDDEN + ko_); \
        cp16(st_ + OFF_AL + soA, pAl + goA + ko_);                           \
        cp16(st_ + OFF_AL + soA + 64 * ROWB, pAl + goA + 64 * HIDDEN + ko_); \
        _Pragma("unroll")                                                    \
        for (int i_ = 0; i_ < 4; ++i_) {                                     \
            cp16(st_ + OFF_BH + soA + i_ * 64 * ROWB,                        \
                 pBh + goA + (size_t)i_ * 64 * HIDDEN + ko_);                \
            cp16(st_ + OFF_BL + soA + i_ * 64 * ROWB,                        \
                 pBl + goA + (size_t)i_ * 64 * HIDDEN + ko_);                \
        }                                                                    \
    } while (0)

    // prologue: stages 0,1
#pragma unroll
    for (int j = 0; j < 2; ++j) {
        ISSUE_LOADS(sb + j * STAGE, (size_t)j * BK);
        asm volatile("cp.async.commit_group;" ::: "memory");
    }

    for (int j = 0; j < NCHUNK; ++j) {
        asm volatile("cp.async.wait_group %0;" :: "n"(1) : "memory");
        __syncthreads();

        if (j + 2 < NCHUNK)
            ISSUE_LOADS(sb + ((j + 2) % NSTAGE) * STAGE, (size_t)(j + 2) * BK);
        asm volatile("cp.async.commit_group;" ::: "memory");

        const uint32_t st = sb + (j % NSTAGE) * STAGE;
#pragma unroll
        for (int s = 0; s < 2; ++s) {
            const uint32_t kb = s * 32;
            uint32_t ah[4][4], al[4][4];
#pragma unroll
            for (int i = 0; i < 4; ++i) {
                ldmx4(ah[i], st + OFF_AH + aOff + i * 16 * ROWB + kb);
                ldmx4(al[i], st + OFF_AL + aOff + i * 16 * ROWB + kb);
            }
#pragma unroll
            for (int t = 0; t < 4; ++t) {
                uint32_t bh[4], bl[4];
                ldmx4(bh, st + OFF_BH + bOff[t] + kb);
                ldmx4(bl, st + OFF_BL + bOff[t] + kb);
#pragma unroll
                for (int i = 0; i < 4; ++i) {
                    mma16816(acc[i][2 * t],     ah[i], bh);
                    mma16816(acc[i][2 * t + 1], ah[i], bh + 2);
                    mma16816(acc[i][2 * t],     al[i], bh);
                    mma16816(acc[i][2 * t + 1], al[i], bh + 2);
                    mma16816(acc[i][2 * t],     ah[i], bl);
                    mma16816(acc[i][2 * t + 1], ah[i], bl + 2);
                }
            }
        }
    }
#undef ISSUE_LOADS

    // epilogue
    const int mBase = rowBase + warpM * 64;
    const int nBase = colBase + warpN * 64;
#pragma unroll
    for (int i = 0; i < 4; ++i) {
#pragma unroll
        for (int n = 0; n < 8; ++n) {
            const int row0 = mBase + i * 16 + (lane >> 2);
            const int col  = nBase + n * 8 + (lane & 3) * 2;
            float2* d0 = (float2*)(C + (size_t)row0 * FFN + col);
            float2* d1 = (float2*)(C + (size_t)(row0 + 8) * FFN + col);
            *d0 = make_float2(acc[i][n][0], acc[i][n][1]);
            *d1 = make_float2(acc[i][n][2], acc[i][n][3]);
        }
    }
}

// ================= launch =================

extern "C" void kernel_launch(void* const* d_in, const int* in_sizes, int n_in,
                              void* d_out, int out_size) {
    const float* A = (const float*)d_in[0];   // [16384, 2048]
    const float* W = (const float*)d_in[1];   // [8, 2048, 8192]
    float* C = (float*)d_out;                 // [16384, 8192]

    __nv_bfloat16 *Ah, *Al, *Bh, *Bl;
    cudaGetSymbolAddress((void**)&Ah, g_Ah);
    cudaGetSymbolAddress((void**)&Al, g_Al);
    cudaGetSymbolAddress((void**)&Bh, g_Bh);
    cudaGetSymbolAddress((void**)&Bl, g_Bl);

    convA_kernel<<<(MTOTAL * HIDDEN) / (256 * 4), 256>>>(A, Ah, Al);
    convW_kernel<<<dim3(FFN / 32, HIDDEN / 128, NGROUPS), 256>>>(W, Bh, Bl);

    cudaFuncSetAttribute(gemm_hmma_kernel,
                         cudaFuncAttributeMaxDynamicSharedMemorySize, SMEM_DYN);
    gemm_hmma_kernel<<<(MTOTAL / BM) * (FFN / BN), 256, SMEM_DYN>>>(C);
}

// round 6
// speedup vs baseline: 5.6594x; 1.4599x over previous
#include <cuda_runtime.h>
#include <cuda_fp16.h>
#include <cstdint>

// Grouped GEMM via fp16-split HMMA: C = Ah*Bh + Al*Bh (A split hi/lo fp16, B single fp16).
// fp32 accum. Tile 128x256, warp tile 64x64, 4-stage cp.async, panel-swizzled CTAs.

static constexpr int HIDDEN = 2048;
static constexpr int FFN    = 8192;
static constexpr int MTOTAL = 16384;
static constexpr int NGROUPS = 8;

#define BM 128
#define BN 256
#define BK 32
static constexpr int NCHUNK = HIDDEN / BK;   // 64

// padded SMEM row: 32 fp16 (64B) + 16B pad = 80B
#define ROWB 80
#define OFF_AH 0
#define OFF_AL (BM * ROWB)                  // 10240
#define OFF_BH (2 * BM * ROWB)              // 20480
#define STAGE  (OFF_BH + BN * ROWB)         // 40960
#define NSTAGE 4
#define SMEM_DYN (NSTAGE * STAGE)           // 163840

// ---- scratch ----
__device__ __half g_Ah[(size_t)MTOTAL * HIDDEN];
__device__ __half g_Al[(size_t)MTOTAL * HIDDEN];
__device__ __half g_Bh[(size_t)NGROUPS * FFN * HIDDEN];   // [g][n][k]

__constant__ int kGroupOff[9] = {0, 1024, 2560, 4608, 6656, 9216, 11264, 14336, 16384};

__device__ __forceinline__ uint32_t pack_h2(__half lo, __half hi) {
    return (uint32_t)__half_as_ushort(lo) | ((uint32_t)__half_as_ushort(hi) << 16);
}

// ================= conversions =================

__global__ void convA_kernel(const float* __restrict__ A,
                             __half* __restrict__ Ah,
                             __half* __restrict__ Al) {
    size_t i = ((size_t)blockIdx.x * blockDim.x + threadIdx.x) * 4;
    float4 v = *(const float4*)(A + i);
    float f[4] = {v.x, v.y, v.z, v.w};
    __half h[4], l[4];
#pragma unroll
    for (int k = 0; k < 4; ++k) {
        h[k] = __float2half(f[k]);
        l[k] = __float2half(f[k] - __half2float(h[k]));
    }
    ((uint32_t*)(Ah + i))[0] = pack_h2(h[0], h[1]);
    ((uint32_t*)(Ah + i))[1] = pack_h2(h[2], h[3]);
    ((uint32_t*)(Al + i))[0] = pack_h2(l[0], l[1]);
    ((uint32_t*)(Al + i))[1] = pack_h2(l[2], l[3]);
}

// W[g][k][n] -> Bh[g][n][k] fp16, 128k x 32n tiles, vectorized 32B stores.
__global__ __launch_bounds__(256)
void convW_kernel(const float* __restrict__ W, __half* __restrict__ Bh) {
    __shared__ float tile[128][33];
    const int g = blockIdx.z;
    const int nBase = blockIdx.x * 32;
    const int kBase = blockIdx.y * 128;
    const int t = threadIdx.x;
    const float* Wg = W + (size_t)g * HIDDEN * FFN;

#pragma unroll
    for (int i = 0; i < 16; ++i) {
        int row = (t >> 5) + 8 * i;
        tile[row][t & 31] = Wg[(size_t)(kBase + row) * FFN + nBase + (t & 31)];
    }
    __syncthreads();

    const int n  = t & 31;
    const int k0 = (t >> 5) * 16;
    uint32_t hp[8];
#pragma unroll
    for (int m = 0; m < 8; ++m) {
        hp[m] = pack_h2(__float2half(tile[k0 + 2 * m][n]),
                        __float2half(tile[k0 + 2 * m + 1][n]));
    }
    size_t o = (size_t)g * FFN * HIDDEN + (size_t)(nBase + n) * HIDDEN + kBase + k0;
    uint4* dh = (uint4*)(Bh + o);
    dh[0] = make_uint4(hp[0], hp[1], hp[2], hp[3]);
    dh[1] = make_uint4(hp[4], hp[5], hp[6], hp[7]);
}

// ================= GEMM =================

__device__ __forceinline__ uint32_t smem_u32(const void* p) {
    uint32_t a;
    asm("{ .reg .u64 t; cvta.to.shared.u64 t, %1; cvt.u32.u64 %0, t; }" : "=r"(a) : "l"(p));
    return a;
}
__device__ __forceinline__ void cp16(uint32_t dst, const void* src) {
    asm volatile("cp.async.cg.shared.global [%0], [%1], 16;\n"
                 :: "r"(dst), "l"(__cvta_generic_to_global(src)));
}
__device__ __forceinline__ void ldmx4(uint32_t* r, uint32_t addr) {
    asm volatile("ldmatrix.sync.aligned.m8n8.x4.shared.b16 {%0,%1,%2,%3}, [%4];"
                 : "=r"(r[0]), "=r"(r[1]), "=r"(r[2]), "=r"(r[3]) : "r"(addr));
}
__device__ __forceinline__ void mma16816(float* c, const uint32_t* a, const uint32_t* b) {
    asm volatile(
        "mma.sync.aligned.m16n8k16.row.col.f32.f16.f16.f32 "
        "{%0,%1,%2,%3}, {%4,%5,%6,%7}, {%8,%9}, {%0,%1,%2,%3};"
        : "+f"(c[0]), "+f"(c[1]), "+f"(c[2]), "+f"(c[3])
        : "r"(a[0]), "r"(a[1]), "r"(a[2]), "r"(a[3]), "r"(b[0]), "r"(b[1]));
}

__global__ __launch_bounds__(256, 1)
void gemm_hmma_kernel(float* __restrict__ C) {
    extern __shared__ char smem[];
    const uint32_t sb = smem_u32(smem);

    const int tid  = threadIdx.x;
    const int warp = tid >> 5;
    const int lane = tid & 31;
    const int warpM = warp & 1;      // 0..1 -> M offset *64
    const int warpN = warp >> 1;     // 0..3 -> N offset *64

    // panel swizzle: 16 m-tiles per panel, column sweep within panel
    const int bid   = blockIdx.x;                 // 0..4095
    const int panel = bid >> 9;
    const int idx   = bid & 511;
    const int rowBase = (panel * 16 + (idx & 15)) * BM;
    const int colBase = (idx >> 4) * BN;

    int g = 0;
#pragma unroll
    for (int i = 1; i < 8; ++i)
        if (rowBase >= kGroupOff[i]) g = i;

    const __half* pAh = g_Ah + (size_t)rowBase * HIDDEN;
    const __half* pAl = g_Al + (size_t)rowBase * HIDDEN;
    const __half* pBh = g_Bh + (size_t)g * FFN * HIDDEN + (size_t)colBase * HIDDEN;

    // copy slots: row = tid>>2 (+64i), 16B chunk = tid&3
    const int lrow = tid >> 2;
    const int lkc  = tid & 3;
    const uint32_t soA = (uint32_t)(lrow * ROWB + lkc * 16);
    const size_t   goA = (size_t)lrow * HIDDEN + lkc * 8;

    // ldmatrix offsets
    const uint32_t aOff = (uint32_t)((warpM * 64 + (lane & 15)) * ROWB + (lane >> 4) * 16);
    uint32_t bOff[4];
#pragma unroll
    for (int i = 0; i < 4; ++i)
        bOff[i] = (uint32_t)((warpN * 64 + i * 16 + (lane & 7) + 8 * ((lane >> 4) & 1)) * ROWB
                             + ((lane >> 3) & 1) * 16);

    float acc[4][8][4];
#pragma unroll
    for (int i = 0; i < 4; ++i)
#pragma unroll
        for (int n = 0; n < 8; ++n)
#pragma unroll
            for (int q = 0; q < 4; ++q) acc[i][n][q] = 0.0f;

#define ISSUE_LOADS(stagep, koff)                                            \
    do {                                                                     \
        const uint32_t st_ = (stagep);                                       \
        const size_t ko_ = (koff);                                           \
        cp16(st_ + OFF_AH + soA, pAh + goA + ko_);                           \
        cp16(st_ + OFF_AH + soA + 64 * ROWB, pAh + goA + 64 * HIDDEN + ko_); \
        cp16(st_ + OFF_AL + soA, pAl + goA + ko_);                           \
        cp16(st_ + OFF_AL + soA + 64 * ROWB, pAl + goA + 64 * HIDDEN + ko_); \
        _Pragma("unroll")                                                    \
        for (int i_ = 0; i_ < 4; ++i_) {                                     \
            cp16(st_ + OFF_BH + soA + i_ * 64 * ROWB,                        \
                 pBh + goA + (size_t)i_ * 64 * HIDDEN + ko_);                \
        }                                                                    \
    } while (0)

    // prologue: stages 0..2
#pragma unroll
    for (int j = 0; j < NSTAGE - 1; ++j) {
        ISSUE_LOADS(sb + j * STAGE, (size_t)j * BK);
        asm volatile("cp.async.commit_group;" ::: "memory");
    }

    for (int j = 0; j < NCHUNK; ++j) {
        asm volatile("cp.async.wait_group %0;" :: "n"(NSTAGE - 2) : "memory");
        __syncthreads();

        if (j + NSTAGE - 1 < NCHUNK)
            ISSUE_LOADS(sb + ((j + NSTAGE - 1) % NSTAGE) * STAGE,
                        (size_t)(j + NSTAGE - 1) * BK);
        asm volatile("cp.async.commit_group;" ::: "memory");

        const uint32_t st = sb + (j % NSTAGE) * STAGE;
#pragma unroll
        for (int s = 0; s < 2; ++s) {
            const uint32_t kb = s * 32;
            uint32_t ah[4][4], al[4][4];
#pragma unroll
            for (int i = 0; i < 4; ++i) {
                ldmx4(ah[i], st + OFF_AH + aOff + i * 16 * ROWB + kb);
                ldmx4(al[i], st + OFF_AL + aOff + i * 16 * ROWB + kb);
            }
#pragma unroll
            for (int t = 0; t < 4; ++t) {
                uint32_t bh[4];
                ldmx4(bh, st + OFF_BH + bOff[t] + kb);
#pragma unroll
                for (int i = 0; i < 4; ++i) {
                    mma16816(acc[i][2 * t],     ah[i], bh);
                    mma16816(acc[i][2 * t + 1], ah[i], bh + 2);
                    mma16816(acc[i][2 * t],     al[i], bh);
                    mma16816(acc[i][2 * t + 1], al[i], bh + 2);
                }
            }
        }
    }
#undef ISSUE_LOADS

    // epilogue
    const int mBase = rowBase + warpM * 64;
    const int nBase = colBase + warpN * 64;
#pragma unroll
    for (int i = 0; i < 4; ++i) {
#pragma unroll
        for (int n = 0; n < 8; ++n) {
            const int row0 = mBase + i * 16 + (lane >> 2);
            const int col  = nBase + n * 8 + (lane & 3) * 2;
            float2* d0 = (float2*)(C + (size_t)row0 * FFN + col);
            float2* d1 = (float2*)(C + (size_t)(row0 + 8) * FFN + col);
            *d0 = make_float2(acc[i][n][0], acc[i][n][1]);
            *d1 = make_float2(acc[i][n][2], acc[i][n][3]);
        }
    }
}

// ================= launch =================

extern "C" void kernel_launch(void* const* d_in, const int* in_sizes, int n_in,
                              void* d_out, int out_size) {
    const float* A = (const float*)d_in[0];   // [16384, 2048]
    const float* W = (const float*)d_in[1];   // [8, 2048, 8192]
    float* C = (float*)d_out;                 // [16384, 8192]

    __half *Ah, *Al, *Bh;
    cudaGetSymbolAddress((void**)&Ah, g_Ah);
    cudaGetSymbolAddress((void**)&Al, g_Al);
    cudaGetSymbolAddress((void**)&Bh, g_Bh);

    convA_kernel<<<(MTOTAL * HIDDEN) / (256 * 4), 256>>>(A, Ah, Al);
    convW_kernel<<<dim3(FFN / 32, HIDDEN / 128, NGROUPS), 256>>>(W, Bh);

    cudaFuncSetAttribute(gemm_hmma_kernel,
                         cudaFuncAttributeMaxDynamicSharedMemorySize, SMEM_DYN);
    gemm_hmma_kernel<<<(MTOTAL / BM) * (FFN / BN), 256, SMEM_DYN>>>(C);
}

// round 7
// speedup vs baseline: 10.1405x; 1.7918x over previous
#include <cuda_runtime.h>
#include <cuda_fp16.h>
#include <cstdint>

// Grouped GEMM, pure fp16 HMMA with fp32 accumulate.
// C = fp16(A) * fp16(W); norm rel_err ~3e-4 (gate: 1e-3).
// Tile 128x256, warp tile 64x64, BK=64, 3-stage cp.async, panel-swizzled CTAs.

static constexpr int HIDDEN = 2048;
static constexpr int FFN    = 8192;
static constexpr int MTOTAL = 16384;
static constexpr int NGROUPS = 8;

#define BM 128
#define BN 256
#define BK 64
static constexpr int NCHUNK = HIDDEN / BK;   // 32

// padded SMEM row: 64 fp16 (128B) + 16B pad = 144B
#define ROWB 144
#define OFF_A 0
#define OFF_B (BM * ROWB)                   // 18432
#define STAGE (OFF_B + BN * ROWB)           // 55296
#define NSTAGE 3
#define SMEM_DYN (NSTAGE * STAGE)           // 165888

// ---- scratch ----
__device__ __half g_Ah[(size_t)MTOTAL * HIDDEN];
__device__ __half g_Bh[(size_t)NGROUPS * FFN * HIDDEN];   // [g][n][k]

__constant__ int kGroupOff[9] = {0, 1024, 2560, 4608, 6656, 9216, 11264, 14336, 16384};

__device__ __forceinline__ uint32_t pack_h2(__half lo, __half hi) {
    return (uint32_t)__half_as_ushort(lo) | ((uint32_t)__half_as_ushort(hi) << 16);
}

// ================= conversions =================

__global__ void convA_kernel(const float* __restrict__ A, __half* __restrict__ Ah) {
    size_t i = ((size_t)blockIdx.x * blockDim.x + threadIdx.x) * 4;
    float4 v = *(const float4*)(A + i);
    ((uint32_t*)(Ah + i))[0] = pack_h2(__float2half(v.x), __float2half(v.y));
    ((uint32_t*)(Ah + i))[1] = pack_h2(__float2half(v.z), __float2half(v.w));
}

// W[g][k][n] -> Bh[g][n][k] fp16, 128k x 32n tiles, vectorized 32B stores.
__global__ __launch_bounds__(256)
void convW_kernel(const float* __restrict__ W, __half* __restrict__ Bh) {
    __shared__ float tile[128][33];
    const int g = blockIdx.z;
    const int nBase = blockIdx.x * 32;
    const int kBase = blockIdx.y * 128;
    const int t = threadIdx.x;
    const float* Wg = W + (size_t)g * HIDDEN * FFN;

#pragma unroll
    for (int i = 0; i < 16; ++i) {
        int row = (t >> 5) + 8 * i;
        tile[row][t & 31] = Wg[(size_t)(kBase + row) * FFN + nBase + (t & 31)];
    }
    __syncthreads();

    const int n  = t & 31;
    const int k0 = (t >> 5) * 16;
    uint32_t hp[8];
#pragma unroll
    for (int m = 0; m < 8; ++m) {
        hp[m] = pack_h2(__float2half(tile[k0 + 2 * m][n]),
                        __float2half(tile[k0 + 2 * m + 1][n]));
    }
    size_t o = (size_t)g * FFN * HIDDEN + (size_t)(nBase + n) * HIDDEN + kBase + k0;
    uint4* dh = (uint4*)(Bh + o);
    dh[0] = make_uint4(hp[0], hp[1], hp[2], hp[3]);
    dh[1] = make_uint4(hp[4], hp[5], hp[6], hp[7]);
}

// ================= GEMM =================

__device__ __forceinline__ uint32_t smem_u32(const void* p) {
    uint32_t a;
    asm("{ .reg .u64 t; cvta.to.shared.u64 t, %1; cvt.u32.u64 %0, t; }" : "=r"(a) : "l"(p));
    return a;
}
__device__ __forceinline__ void cp16(uint32_t dst, const void* src) {
    asm volatile("cp.async.cg.shared.global [%0], [%1], 16;\n"
                 :: "r"(dst), "l"(__cvta_generic_to_global(src)));
}
__device__ __forceinline__ void ldmx4(uint32_t* r, uint32_t addr) {
    asm volatile("ldmatrix.sync.aligned.m8n8.x4.shared.b16 {%0,%1,%2,%3}, [%4];"
                 : "=r"(r[0]), "=r"(r[1]), "=r"(r[2]), "=r"(r[3]) : "r"(addr));
}
__device__ __forceinline__ void mma16816(float* c, const uint32_t* a, const uint32_t* b) {
    asm volatile(
        "mma.sync.aligned.m16n8k16.row.col.f32.f16.f16.f32 "
        "{%0,%1,%2,%3}, {%4,%5,%6,%7}, {%8,%9}, {%0,%1,%2,%3};"
        : "+f"(c[0]), "+f"(c[1]), "+f"(c[2]), "+f"(c[3])
        : "r"(a[0]), "r"(a[1]), "r"(a[2]), "r"(a[3]), "r"(b[0]), "r"(b[1]));
}

__global__ __launch_bounds__(256, 1)
void gemm_hmma_kernel(float* __restrict__ C) {
    extern __shared__ char smem[];
    const uint32_t sb = smem_u32(smem);

    const int tid  = threadIdx.x;
    const int warp = tid >> 5;
    const int lane = tid & 31;
    const int warpM = warp & 1;      // 0..1 -> M offset *64
    const int warpN = warp >> 1;     // 0..3 -> N offset *64

    // panel swizzle: 16 m-tiles per panel, column sweep within panel
    const int bid   = blockIdx.x;                 // 0..4095
    const int panel = bid >> 9;
    const int idx   = bid & 511;
    const int rowBase = (panel * 16 + (idx & 15)) * BM;
    const int colBase = (idx >> 4) * BN;

    int g = 0;
#pragma unroll
    for (int i = 1; i < 8; ++i)
        if (rowBase >= kGroupOff[i]) g = i;

    const __half* pA = g_Ah + (size_t)rowBase * HIDDEN;
    const __half* pB = g_Bh + (size_t)g * FFN * HIDDEN + (size_t)colBase * HIDDEN;

    // copy slots: slot = tid + 256*i -> row = slot>>3, 16B chunk = slot&7
    const int crow = tid >> 3;          // 0..31
    const int cchk = tid & 7;           // 0..7
    const uint32_t so = (uint32_t)(crow * ROWB + cchk * 16);
    const size_t   go = (size_t)crow * HIDDEN + cchk * 8;

    // ldmatrix offsets
    const uint32_t aOff = (uint32_t)((warpM * 64 + (lane & 15)) * ROWB + (lane >> 4) * 16);
    uint32_t bOff[4];
#pragma unroll
    for (int i = 0; i < 4; ++i)
        bOff[i] = (uint32_t)((warpN * 64 + i * 16 + (lane & 7) + 8 * ((lane >> 4) & 1)) * ROWB
                             + ((lane >> 3) & 1) * 16);

    float acc[4][8][4];
#pragma unroll
    for (int i = 0; i < 4; ++i)
#pragma unroll
        for (int n = 0; n < 8; ++n)
#pragma unroll
            for (int q = 0; q < 4; ++q) acc[i][n][q] = 0.0f;

    // A: 128 rows x 8 chunks = 1024 slots -> 4/thread; B: 256 rows -> 8/thread
#define ISSUE_LOADS(stagep, koff)                                              \
    do {                                                                       \
        const uint32_t st_ = (stagep);                                         \
        const size_t ko_ = (koff);                                             \
        _Pragma("unroll")                                                      \
        for (int i_ = 0; i_ < 4; ++i_)                                         \
            cp16(st_ + OFF_A + so + i_ * 32 * ROWB,                            \
                 pA + go + (size_t)i_ * 32 * HIDDEN + ko_);                    \
        _Pragma("unroll")                                                      \
        for (int i_ = 0; i_ < 8; ++i_)                                         \
            cp16(st_ + OFF_B + so + i_ * 32 * ROWB,                            \
                 pB + go + (size_t)i_ * 32 * HIDDEN + ko_);                    \
    } while (0)

    // prologue: stages 0,1
#pragma unroll
    for (int j = 0; j < NSTAGE - 1; ++j) {
        ISSUE_LOADS(sb + j * STAGE, (size_t)j * BK);
        asm volatile("cp.async.commit_group;" ::: "memory");
    }

    for (int j = 0; j < NCHUNK; ++j) {
        asm volatile("cp.async.wait_group %0;" :: "n"(NSTAGE - 2) : "memory");
        __syncthreads();

        if (j + NSTAGE - 1 < NCHUNK)
            ISSUE_LOADS(sb + ((j + NSTAGE - 1) % NSTAGE) * STAGE,
                        (size_t)(j + NSTAGE - 1) * BK);
        asm volatile("cp.async.commit_group;" ::: "memory");

        const uint32_t st = sb + (j % NSTAGE) * STAGE;
#pragma unroll
        for (int s = 0; s < 4; ++s) {            // 4 k16-steps per BK=64 chunk
            const uint32_t kb = s * 32;
            uint32_t ah[4][4];
#pragma unroll
            for (int i = 0; i < 4; ++i)
                ldmx4(ah[i], st + OFF_A + aOff + i * 16 * ROWB + kb);
#pragma unroll
            for (int t = 0; t < 4; ++t) {
                uint32_t bh[4];
                ldmx4(bh, st + OFF_B + bOff[t] + kb);
#pragma unroll
                for (int i = 0; i < 4; ++i) {
                    mma16816(acc[i][2 * t],     ah[i], bh);
                    mma16816(acc[i][2 * t + 1], ah[i], bh + 2);
                }
            }
        }
    }
#undef ISSUE_LOADS

    // epilogue
    const int mBase = rowBase + warpM * 64;
    const int nBase = colBase + warpN * 64;
#pragma unroll
    for (int i = 0; i < 4; ++i) {
#pragma unroll
        for (int n = 0; n < 8; ++n) {
            const int row0 = mBase + i * 16 + (lane >> 2);
            const int col  = nBase + n * 8 + (lane & 3) * 2;
            float2* d0 = (float2*)(C + (size_t)row0 * FFN + col);
            float2* d1 = (float2*)(C + (size_t)(row0 + 8) * FFN + col);
            *d0 = make_float2(acc[i][n][0], acc[i][n][1]);
            *d1 = make_float2(acc[i][n][2], acc[i][n][3]);
        }
    }
}

// ================= launch =================

extern "C" void kernel_launch(void* const* d_in, const int* in_sizes, int n_in,
                              void* d_out, int out_size) {
    const float* A = (const float*)d_in[0];   // [16384, 2048]
    const float* W = (const float*)d_in[1];   // [8, 2048, 8192]
    float* C = (float*)d_out;                 // [16384, 8192]

    __half *Ah, *Bh;
    cudaGetSymbolAddress((void**)&Ah, g_Ah);
    cudaGetSymbolAddress((void**)&Bh, g_Bh);

    convA_kernel<<<(MTOTAL * HIDDEN) / (256 * 4), 256>>>(A, Ah);
    convW_kernel<<<dim3(FFN / 32, HIDDEN / 128, NGROUPS), 256>>>(W, Bh);

    cudaFuncSetAttribute(gemm_hmma_kernel,
                         cudaFuncAttributeMaxDynamicSharedMemorySize, SMEM_DYN);
    gemm_hmma_kernel<<<(MTOTAL / BM) * (FFN / BN), 256, SMEM_DYN>>>(C);
}